// round 4
// baseline (speedup 1.0000x reference)
#include <cuda_runtime.h>
#include <cstdint>

// GRU via warp-level HMMA (mma.sync m16n8k16 bf16->fp32), no 'a'-feature PTX.
// 128 CTAs x 256 threads; each CTA owns 8 batch rows for all 784 steps.
// Per step: gh[384,8] = Wh[384,128] @ h[8,128]^T as 24 M-tiles x 8 K-tiles.
// Precision: Wh = W_hi + W_lo (bf16 split), h = h_hi + h_lo (bf16 split);
// gh = W_hi*h_hi + W_hi*h_lo + W_lo*h_hi accumulated in fp32 C-frags.
// W_hi: register-resident A fragments (96 regs/thread).
// W_lo: SMEM, fragment-interleaved, one ld.shared.v4 per fragment.

#define HID   128
#define SEQ   784
#define ROWS  8
#define NT    256
#define NCTA  128

#define GH_STRIDE 40                   // bytes per gate row (8 n * 4B + 8 pad)
#define B_STRIDE  272                  // bytes per n row of h tiles (256 + 16 pad)

#define OFF_WLO 0                      // 24*8*32*16 = 98304 B
#define OFF_GH  98304                  // 384*40 = 15360 B
#define OFF_BH  (98304 + 15360)        // 8*272 = 2176 B
#define OFF_BL  (OFF_BH + 2176)        // 2176 B
#define SMEM_BYTES (OFF_BL + 2176)     // 120192 B

__device__ __forceinline__ uint16_t f2bf(float f) {
    uint16_t h;
    asm("cvt.rn.bf16.f32 %0, %1;" : "=h"(h) : "f"(f));
    return h;
}
__device__ __forceinline__ float bf2f(uint16_t h) {
    return __uint_as_float((uint32_t)h << 16);
}
__device__ __forceinline__ uint32_t pack_hi(float w0, float w1) {
    return (uint32_t)f2bf(w0) | ((uint32_t)f2bf(w1) << 16);
}
__device__ __forceinline__ uint32_t pack_lo(float w0, float w1) {
    float r0 = w0 - bf2f(f2bf(w0));
    float r1 = w1 - bf2f(f2bf(w1));
    return (uint32_t)f2bf(r0) | ((uint32_t)f2bf(r1) << 16);
}
__device__ __forceinline__ void mma16816(float* c, const uint32_t* a,
                                         uint32_t b0, uint32_t b1) {
    asm volatile(
        "mma.sync.aligned.m16n8k16.row.col.f32.bf16.bf16.f32 "
        "{%0,%1,%2,%3}, {%4,%5,%6,%7}, {%8,%9}, {%0,%1,%2,%3};"
        : "+f"(c[0]), "+f"(c[1]), "+f"(c[2]), "+f"(c[3])
        : "r"(a[0]), "r"(a[1]), "r"(a[2]), "r"(a[3]), "r"(b0), "r"(b1));
}
__device__ __forceinline__ float fast_sigmoid(float x) {
    float e = __expf(-x);
    return __fdividef(1.0f, 1.0f + e);
}
__device__ __forceinline__ float fast_tanh(float x) {
    float e = __expf(-2.0f * x);
    return fmaf(2.0f, __fdividef(1.0f, 1.0f + e), -1.0f);
}

extern __shared__ __align__(16) char smem[];

__global__ __launch_bounds__(NT, 1)
void gru_hmma_kernel(const float* __restrict__ x,
                     const float* __restrict__ Wi,
                     const float* __restrict__ bi,
                     const float* __restrict__ Wh,
                     const float* __restrict__ bh,
                     const float* __restrict__ Wfc,
                     const float* __restrict__ bfc,
                     float* __restrict__ out) {
    const int tid  = threadIdx.x;
    const int lane = tid & 31;
    const int wid  = tid >> 5;
    const int row0 = blockIdx.x * ROWS;

    // ---- prologue: W_hi -> register A-fragments; W_lo -> SMEM fragment array
    uint32_t af[3][8][4];
#pragma unroll
    for (int j = 0; j < 3; ++j) {
        const int m = wid * 3 + j;                 // M-tile 0..23 (gates 16m..16m+15)
#pragma unroll
        for (int kt = 0; kt < 8; ++kt) {
            uint32_t lo[4];
#pragma unroll
            for (int r = 0; r < 4; ++r) {
                const int g = m * 16 + (lane >> 2) + ((r & 1) ? 8 : 0);
                const int k = kt * 16 + (lane & 3) * 2 + ((r & 2) ? 8 : 0);
                const float w0 = Wh[g * HID + k];
                const float w1 = Wh[g * HID + k + 1];
                af[j][kt][r] = pack_hi(w0, w1);
                lo[r]        = pack_lo(w0, w1);
            }
            *(uint4*)(smem + OFF_WLO + (((m * 8) + kt) * 32 + lane) * 16) =
                make_uint4(lo[0], lo[1], lo[2], lo[3]);
        }
    }
    // zero h hi/lo tiles (contiguous 2*2176 B)
    for (int idx = tid; idx < (2 * 2176) / 4; idx += NT)
        ((uint32_t*)(smem + OFF_BH))[idx] = 0u;

    // gate-thread constants (tid < 128 meaningful; masked index keeps loads legal)
    const int   i   = tid & 127;
    const float wi0 = Wi[i];
    const float wi1 = Wi[i + HID];
    const float wi2 = Wi[i + 2 * HID];
    const float br  = bi[i] + bh[i];
    const float bz  = bi[i + HID] + bh[i + HID];
    const float bni = bi[i + 2 * HID];
    const float bnh = bh[i + 2 * HID];

    float hprev[ROWS];
#pragma unroll
    for (int r = 0; r < ROWS; ++r) hprev[r] = 0.0f;

    const float* xrow = x + (long)row0 * SEQ;
    const bool is_gate = (tid < 128);

    __syncthreads();

#pragma unroll 1
    for (int t = 0; t < SEQ; ++t) {
        // ---- phase 1: all 8 warps do the 3-pass MMA ----
        float C[3][4];
#pragma unroll
        for (int j = 0; j < 3; ++j)
#pragma unroll
            for (int r = 0; r < 4; ++r) C[j][r] = 0.0f;

        float xv[ROWS];
        if (is_gate) {
#pragma unroll
            for (int r = 0; r < ROWS; ++r) xv[r] = __ldg(xrow + (long)r * SEQ + t);
        }

        const int nb = (lane >> 2) * B_STRIDE;          // n row base
#pragma unroll
        for (int kt = 0; kt < 8; ++kt) {
            const int kb = kt * 32 + (lane & 3) * 4;    // byte offset of k within row
            const uint32_t bh0 = *(const uint32_t*)(smem + OFF_BH + nb + kb);
            const uint32_t bh1 = *(const uint32_t*)(smem + OFF_BH + nb + kb + 16);
            const uint32_t bl0 = *(const uint32_t*)(smem + OFF_BL + nb + kb);
            const uint32_t bl1 = *(const uint32_t*)(smem + OFF_BL + nb + kb + 16);
#pragma unroll
            for (int j = 0; j < 3; ++j) {
                mma16816(C[j], af[j][kt], bh0, bh1);          // W_hi * h_hi
                mma16816(C[j], af[j][kt], bl0, bl1);          // W_hi * h_lo
                const uint4 wl = *(const uint4*)(smem + OFF_WLO +
                                  (((wid * 3 + j) * 8 + kt) * 32 + lane) * 16);
                const uint32_t wla[4] = {wl.x, wl.y, wl.z, wl.w};
                mma16816(C[j], wla, bh0, bh1);                // W_lo * h_hi
            }
        }

        // ---- phase 2: spill gh C-frags to SMEM [g][n] (stride 40B) ----
#pragma unroll
        for (int j = 0; j < 3; ++j) {
            const int g0 = (wid * 3 + j) * 16 + (lane >> 2);
            const int cb = (lane & 3) * 8;
            *(float2*)(smem + OFF_GH + g0 * GH_STRIDE + cb) =
                make_float2(C[j][0], C[j][1]);
            *(float2*)(smem + OFF_GH + (g0 + 8) * GH_STRIDE + cb) =
                make_float2(C[j][2], C[j][3]);
        }
        __syncthreads();

        // ---- phase 3: gate math on 128 threads; write next h hi/lo tiles ----
        if (is_gate) {
            float gr[8], gz[8], gn[8];
            const char* pr = smem + OFF_GH + i * GH_STRIDE;
            const char* pz = smem + OFF_GH + (i + 128) * GH_STRIDE;
            const char* pn = smem + OFF_GH + (i + 256) * GH_STRIDE;
#pragma unroll
            for (int q = 0; q < 4; ++q) {
                float2 a = *(const float2*)(pr + q * 8);
                gr[2 * q] = a.x; gr[2 * q + 1] = a.y;
                float2 b = *(const float2*)(pz + q * 8);
                gz[2 * q] = b.x; gz[2 * q + 1] = b.y;
                float2 c = *(const float2*)(pn + q * 8);
                gn[2 * q] = c.x; gn[2 * q + 1] = c.y;
            }
#pragma unroll
            for (int r = 0; r < ROWS; ++r) {
                const float rr = fast_sigmoid(gr[r] + fmaf(xv[r], wi0, br));
                const float zz = fast_sigmoid(gz[r] + fmaf(xv[r], wi1, bz));
                const float nn = fast_tanh(fmaf(xv[r], wi2, bni) + rr * (gn[r] + bnh));
                const float h  = nn + zz * (hprev[r] - nn);
                hprev[r] = h;
                const uint16_t hb = f2bf(h);
                const uint16_t lb = f2bf(h - bf2f(hb));
                *(uint16_t*)(smem + OFF_BH + r * B_STRIDE + i * 2) = hb;
                *(uint16_t*)(smem + OFF_BL + r * B_STRIDE + i * 2) = lb;
            }
        }
        __syncthreads();
    }

    // ---- final FC: logits = h @ Wfc^T + bfc ----
    float* hf = (float*)(smem + OFF_GH);   // reuse: hf[k][n], 128x8 fp32
    if (is_gate) {
#pragma unroll
        for (int r = 0; r < ROWS; ++r) hf[i * ROWS + r] = hprev[r];
    }
    __syncthreads();

    if (tid < ROWS * 10) {
        const int r = tid / 10;
        const int o = tid - r * 10;
        float s = bfc[o];
        const float* wf = Wfc + o * HID;
#pragma unroll 8
        for (int k = 0; k < HID; ++k) s = fmaf(hf[k * ROWS + r], wf[k], s);
        out[(long)(row0 + r) * 10 + o] = s;
    }
}

extern "C" void kernel_launch(void* const* d_in, const int* in_sizes, int n_in,
                              void* d_out, int out_size) {
    const float* x   = (const float*)d_in[0];
    const float* Wi  = (const float*)d_in[1];
    const float* bi  = (const float*)d_in[2];
    const float* Wh  = (const float*)d_in[3];
    const float* bh  = (const float*)d_in[4];
    const float* Wfc = (const float*)d_in[5];
    const float* bfc = (const float*)d_in[6];
    float* out = (float*)d_out;

    cudaFuncSetAttribute(gru_hmma_kernel,
                         cudaFuncAttributeMaxDynamicSharedMemorySize, SMEM_BYTES);
    gru_hmma_kernel<<<NCTA, NT, SMEM_BYTES>>>(x, Wi, bi, Wh, bh, Wfc, bfc, out);
}

// round 5
// speedup vs baseline: 1.1951x; 1.1951x over previous
#include <cuda_runtime.h>
#include <cstdint>

// GRU via warp-level HMMA (mma.sync m16n8k16 bf16->fp32).
// 128 CTAs x 256 threads; CTA owns 8 batch rows for all 784 steps.
// Gate-colocated M-tile mapping: warp w computes M-tiles {r,z,n} of hidden
// units [16w,16w+16), so each thread's C fragments hold gr/gz/gn for its own
// (i, n) pairs -> gate math in registers, no gh SMEM round-trip, 1 bar/step.
// Precision: Wh = W_hi + W_lo, h = h_hi + h_lo (bf16 splits), 3-pass fp32 acc.
// W_hi register-resident (96 regs); W_lo in SMEM fragment-interleaved.

#define HID   128
#define SEQ   784
#define ROWS  8
#define NT    256
#define NCTA  128

#define B_STRIDE  272                    // bytes per n row (256 + 16 pad)
#define XS_STRIDE 788                    // floats per x row (784 + 4 pad)

#define OFF_WLO 0                        // 24*8*32*16 = 98304 B
#define OFF_XS  98304                    // 8*788*4 = 25216 B
#define OFF_BH  123520                   // 2 bufs x 2176
#define OFF_BL  127872                   // 2 bufs x 2176
#define SMEM_BYTES (127872 + 4352)       // 132224 B

__device__ __forceinline__ uint16_t f2bf(float f) {
    uint16_t h;
    asm("cvt.rn.bf16.f32 %0, %1;" : "=h"(h) : "f"(f));
    return h;
}
__device__ __forceinline__ float bf2f(uint16_t h) {
    return __uint_as_float((uint32_t)h << 16);
}
__device__ __forceinline__ uint32_t pack_hi(float w0, float w1) {
    return (uint32_t)f2bf(w0) | ((uint32_t)f2bf(w1) << 16);
}
__device__ __forceinline__ uint32_t pack_lo(float w0, float w1) {
    float r0 = w0 - bf2f(f2bf(w0));
    float r1 = w1 - bf2f(f2bf(w1));
    return (uint32_t)f2bf(r0) | ((uint32_t)f2bf(r1) << 16);
}
__device__ __forceinline__ void mma16816(float* c, const uint32_t* a,
                                         uint32_t b0, uint32_t b1) {
    asm volatile(
        "mma.sync.aligned.m16n8k16.row.col.f32.bf16.bf16.f32 "
        "{%0,%1,%2,%3}, {%4,%5,%6,%7}, {%8,%9}, {%0,%1,%2,%3};"
        : "+f"(c[0]), "+f"(c[1]), "+f"(c[2]), "+f"(c[3])
        : "r"(a[0]), "r"(a[1]), "r"(a[2]), "r"(a[3]), "r"(b0), "r"(b1));
}
__device__ __forceinline__ float fast_sigmoid(float x) {
    float e = __expf(-x);
    return __fdividef(1.0f, 1.0f + e);
}
__device__ __forceinline__ float fast_tanh(float x) {
    float e = __expf(-2.0f * x);
    return fmaf(2.0f, __fdividef(1.0f, 1.0f + e), -1.0f);
}

extern __shared__ __align__(16) char smem[];

__global__ __launch_bounds__(NT, 1)
void gru_hmma2_kernel(const float* __restrict__ x,
                      const float* __restrict__ Wi,
                      const float* __restrict__ bi,
                      const float* __restrict__ Wh,
                      const float* __restrict__ bh,
                      const float* __restrict__ Wfc,
                      const float* __restrict__ bfc,
                      float* __restrict__ out) {
    const int tid  = threadIdx.x;
    const int lane = tid & 31;
    const int wid  = tid >> 5;
    const int row0 = blockIdx.x * ROWS;

    // this thread's ownership after MMA
    const int i0 = 16 * wid + (lane >> 2);   // hidden unit (and i0+8)
    const int n0 = 2 * (lane & 3);           // batch col (and n0+1)

    // ---- prologue: W_hi -> regs, W_lo -> SMEM (gate-colocated tiles) ----
    uint32_t af[3][8][4];
#pragma unroll
    for (int j = 0; j < 3; ++j) {            // j: 0=r,1=z,2=n gate tile
#pragma unroll
        for (int kt = 0; kt < 8; ++kt) {
            uint32_t lo[4];
#pragma unroll
            for (int r = 0; r < 4; ++r) {
                const int g = j * HID + 16 * wid + (lane >> 2) + ((r & 1) ? 8 : 0);
                const int k = kt * 16 + (lane & 3) * 2 + ((r & 2) ? 8 : 0);
                const float w0 = Wh[g * HID + k];
                const float w1 = Wh[g * HID + k + 1];
                af[j][kt][r] = pack_hi(w0, w1);
                lo[r]        = pack_lo(w0, w1);
            }
            *(uint4*)(smem + OFF_WLO + (((wid * 3 + j) * 8 + kt) * 32 + lane) * 16) =
                make_uint4(lo[0], lo[1], lo[2], lo[3]);
        }
    }
    // x slice -> SMEM: xs[r][t]
    {
        float* xs = (float*)(smem + OFF_XS);
        for (int idx = tid; idx < ROWS * SEQ; idx += NT) {
            const int r = idx / SEQ;
            const int t = idx - r * SEQ;
            xs[r * XS_STRIDE + t] = x[(long)(row0 + r) * SEQ + t];
        }
    }
    // zero h hi/lo tiles (both buffers, 8704 B total)
    for (int idx = tid; idx < 2176; idx += NT)
        ((uint32_t*)(smem + OFF_BH))[idx] = 0u;

    // per-thread gate constants for units i0, i1=i0+8
    const float wi0a = Wi[i0],          wi0b = Wi[i0 + 8];
    const float wi1a = Wi[i0 + HID],    wi1b = Wi[i0 + 8 + HID];
    const float wi2a = Wi[i0 + 2*HID],  wi2b = Wi[i0 + 8 + 2*HID];
    const float bra  = bi[i0] + bh[i0],               brb = bi[i0+8] + bh[i0+8];
    const float bza  = bi[i0+HID] + bh[i0+HID],       bzb = bi[i0+8+HID] + bh[i0+8+HID];
    const float bnia = bi[i0+2*HID],                  bnib = bi[i0+8+2*HID];
    const float bnha = bh[i0+2*HID],                  bnhb = bh[i0+8+2*HID];

    float hprev[4];                      // (i0,n0),(i0,n1),(i1,n0),(i1,n1)
#pragma unroll
    for (int q = 0; q < 4; ++q) hprev[q] = 0.0f;

    const float* xs0 = (const float*)(smem + OFF_XS) + n0 * XS_STRIDE;
    const float* xs1 = xs0 + XS_STRIDE;

    __syncthreads();

#pragma unroll 1
    for (int t = 0; t < SEQ; ++t) {
        const int rsel = (t & 1) * 2176;
        const int wsel = ((t + 1) & 1) * 2176;

        float C[3][4];
#pragma unroll
        for (int j = 0; j < 3; ++j)
#pragma unroll
            for (int q = 0; q < 4; ++q) C[j][q] = 0.0f;

        const float xv0 = xs0[t];
        const float xv1 = xs1[t];

        const int nb = (lane >> 2) * B_STRIDE;
#pragma unroll
        for (int kt = 0; kt < 8; ++kt) {
            const int kb = kt * 32 + (lane & 3) * 4;
            const uint32_t bh0 = *(const uint32_t*)(smem + OFF_BH + rsel + nb + kb);
            const uint32_t bh1 = *(const uint32_t*)(smem + OFF_BH + rsel + nb + kb + 16);
            const uint32_t bl0 = *(const uint32_t*)(smem + OFF_BL + rsel + nb + kb);
            const uint32_t bl1 = *(const uint32_t*)(smem + OFF_BL + rsel + nb + kb + 16);
#pragma unroll
            for (int j = 0; j < 3; ++j) {
                mma16816(C[j], af[j][kt], bh0, bh1);          // W_hi * h_hi
                mma16816(C[j], af[j][kt], bl0, bl1);          // W_hi * h_lo
                const uint4 wl = *(const uint4*)(smem + OFF_WLO +
                                  (((wid * 3 + j) * 8 + kt) * 32 + lane) * 16);
                const uint32_t wla[4] = {wl.x, wl.y, wl.z, wl.w};
                mma16816(C[j], wla, bh0, bh1);                // W_lo * h_hi
            }
        }

        // ---- gate math in registers; store h hi/lo for next step ----
        char* bhp = smem + OFF_BH + wsel;
        char* blp = smem + OFF_BL + wsel;
#pragma unroll
        for (int q = 0; q < 4; ++q) {
            const bool second = (q >= 2);
            const int  i  = second ? (i0 + 8) : i0;
            const int  n  = (q & 1) ? (n0 + 1) : n0;
            const float xv  = (q & 1) ? xv1 : xv0;
            const float wiA = second ? wi0b : wi0a;
            const float wiB = second ? wi1b : wi1a;
            const float wiC = second ? wi2b : wi2a;
            const float bR  = second ? brb  : bra;
            const float bZ  = second ? bzb  : bza;
            const float bNi = second ? bnib : bnia;
            const float bNh = second ? bnhb : bnha;

            const float rr = fast_sigmoid(C[0][q] + fmaf(xv, wiA, bR));
            const float zz = fast_sigmoid(C[1][q] + fmaf(xv, wiB, bZ));
            const float nn = fast_tanh(fmaf(xv, wiC, bNi) + rr * (C[2][q] + bNh));
            const float h  = nn + zz * (hprev[q] - nn);
            hprev[q] = h;

            const uint16_t hb = f2bf(h);
            const uint16_t lb = f2bf(h - bf2f(hb));
            *(uint16_t*)(bhp + n * B_STRIDE + i * 2) = hb;
            *(uint16_t*)(blp + n * B_STRIDE + i * 2) = lb;
        }
        __syncthreads();
    }

    // ---- final FC: logits = h @ Wfc^T + bfc ----
    float* hf = (float*)(smem + OFF_XS);   // reuse: hf[i][n]
    {
        hf[i0 * ROWS + n0]           = hprev[0];
        hf[i0 * ROWS + n0 + 1]       = hprev[1];
        hf[(i0 + 8) * ROWS + n0]     = hprev[2];
        hf[(i0 + 8) * ROWS + n0 + 1] = hprev[3];
    }
    __syncthreads();

    if (tid < ROWS * 10) {
        const int r = tid / 10;
        const int o = tid - r * 10;
        float s = bfc[o];
        const float* wf = Wfc + o * HID;
#pragma unroll 8
        for (int k = 0; k < HID; ++k) s = fmaf(hf[k * ROWS + r], wf[k], s);
        out[(long)(row0 + r) * 10 + o] = s;
    }
}

extern "C" void kernel_launch(void* const* d_in, const int* in_sizes, int n_in,
                              void* d_out, int out_size) {
    const float* x   = (const float*)d_in[0];
    const float* Wi  = (const float*)d_in[1];
    const float* bi  = (const float*)d_in[2];
    const float* Wh  = (const float*)d_in[3];
    const float* bh  = (const float*)d_in[4];
    const float* Wfc = (const float*)d_in[5];
    const float* bfc = (const float*)d_in[6];
    float* out = (float*)d_out;

    cudaFuncSetAttribute(gru_hmma2_kernel,
                         cudaFuncAttributeMaxDynamicSharedMemorySize, SMEM_BYTES);
    gru_hmma2_kernel<<<NCTA, NT, SMEM_BYTES>>>(x, Wi, bi, Wh, bh, Wfc, bfc, out);
}

// round 6
// speedup vs baseline: 1.2474x; 1.0438x over previous
#include <cuda_runtime.h>
#include <cstdint>

// GRU via warp-level HMMA (mma.sync m16n8k16 bf16->fp32).
// 128 CTAs x 256 threads; CTA owns 8 batch rows for all 784 steps.
// Gate-colocated M-tiles: warp w computes r/z/n gates of hidden units
// [16w,16w+16) -> gate math fully in registers, 1 barrier/step.
// Precision: Wh = W_hi + W_lo, h = h_hi + h_lo (bf16 splits), 3-pass fp32 acc.
// W_hi register-resident; W_lo SMEM fragment-interleaved (1 LDS.128 each).
// h tiles stored in HMMA-fragment word order -> 1 LDS.64 per operand tile.
// Gates use MUFU.TANH (tanh.approx.f32): 12 MUFU/thread/step vs 24.

#define HID   128
#define SEQ   784
#define ROWS  8
#define NT    256
#define NCTA  128

#define B_STRIDE  272                    // bytes per n row (256 + 16 pad)
#define XS_STRIDE 788                    // floats per x row (784 + 4 pad)

#define OFF_WLO 0                        // 24*8*32*16 = 98304 B
#define OFF_XS  98304                    // 8*788*4 = 25216 B
#define OFF_BH  123520                   // 2 bufs x 2176
#define OFF_BL  127872                   // 2 bufs x 2176
#define SMEM_BYTES (127872 + 4352)       // 132224 B

__device__ __forceinline__ uint16_t f2bf(float f) {
    uint16_t h;
    asm("cvt.rn.bf16.f32 %0, %1;" : "=h"(h) : "f"(f));
    return h;
}
__device__ __forceinline__ float bf2f(uint16_t h) {
    return __uint_as_float((uint32_t)h << 16);
}
__device__ __forceinline__ uint32_t pack_hi(float w0, float w1) {
    return (uint32_t)f2bf(w0) | ((uint32_t)f2bf(w1) << 16);
}
__device__ __forceinline__ uint32_t pack_lo(float w0, float w1) {
    float r0 = w0 - bf2f(f2bf(w0));
    float r1 = w1 - bf2f(f2bf(w1));
    return (uint32_t)f2bf(r0) | ((uint32_t)f2bf(r1) << 16);
}
__device__ __forceinline__ void mma16816(float* c, const uint32_t* a,
                                         uint32_t b0, uint32_t b1) {
    asm volatile(
        "mma.sync.aligned.m16n8k16.row.col.f32.bf16.bf16.f32 "
        "{%0,%1,%2,%3}, {%4,%5,%6,%7}, {%8,%9}, {%0,%1,%2,%3};"
        : "+f"(c[0]), "+f"(c[1]), "+f"(c[2]), "+f"(c[3])
        : "r"(a[0]), "r"(a[1]), "r"(a[2]), "r"(a[3]), "r"(b0), "r"(b1));
}
__device__ __forceinline__ float mufu_tanh(float x) {
    float r;
    asm("tanh.approx.f32 %0, %1;" : "=f"(r) : "f"(x));
    return r;
}

extern __shared__ __align__(16) char smem[];

__global__ __launch_bounds__(NT, 1)
void gru_hmma3_kernel(const float* __restrict__ x,
                      const float* __restrict__ Wi,
                      const float* __restrict__ bi,
                      const float* __restrict__ Wh,
                      const float* __restrict__ bh,
                      const float* __restrict__ Wfc,
                      const float* __restrict__ bfc,
                      float* __restrict__ out) {
    const int tid  = threadIdx.x;
    const int lane = tid & 31;
    const int wid  = tid >> 5;
    const int row0 = blockIdx.x * ROWS;

    // ownership after MMA: units (i0, i0+8), batch cols (n0, n0+1)
    const int i0 = 16 * wid + (lane >> 2);
    const int n0 = 2 * (lane & 3);

    // ---- prologue: W_hi -> regs, W_lo -> SMEM (gate-colocated tiles) ----
    uint32_t af[3][8][4];
#pragma unroll
    for (int j = 0; j < 3; ++j) {            // 0=r,1=z,2=n
#pragma unroll
        for (int kt = 0; kt < 8; ++kt) {
            uint32_t lo[4];
#pragma unroll
            for (int r = 0; r < 4; ++r) {
                const int g = j * HID + 16 * wid + (lane >> 2) + ((r & 1) ? 8 : 0);
                const int k = kt * 16 + (lane & 3) * 2 + ((r & 2) ? 8 : 0);
                const float w0 = Wh[g * HID + k];
                const float w1 = Wh[g * HID + k + 1];
                af[j][kt][r] = pack_hi(w0, w1);
                lo[r]        = pack_lo(w0, w1);
            }
            *(uint4*)(smem + OFF_WLO + (((wid * 3 + j) * 8 + kt) * 32 + lane) * 16) =
                make_uint4(lo[0], lo[1], lo[2], lo[3]);
        }
    }
    // x slice -> SMEM
    {
        float* xs = (float*)(smem + OFF_XS);
        for (int idx = tid; idx < ROWS * SEQ; idx += NT) {
            const int r = idx / SEQ;
            const int t = idx - r * SEQ;
            xs[r * XS_STRIDE + t] = x[(long)(row0 + r) * SEQ + t];
        }
    }
    // zero h hi/lo tiles (both buffers)
    for (int idx = tid; idx < 2176; idx += NT)
        ((uint32_t*)(smem + OFF_BH))[idx] = 0u;

    // gate constants (r/z halved for sigmoid-via-tanh folding)
    const float wi0a = 0.5f * Wi[i0],         wi0b = 0.5f * Wi[i0 + 8];
    const float wi1a = 0.5f * Wi[i0 + HID],   wi1b = 0.5f * Wi[i0 + 8 + HID];
    const float wi2a = Wi[i0 + 2*HID],        wi2b = Wi[i0 + 8 + 2*HID];
    const float bra  = 0.5f * (bi[i0] + bh[i0]);
    const float brb  = 0.5f * (bi[i0+8] + bh[i0+8]);
    const float bza  = 0.5f * (bi[i0+HID] + bh[i0+HID]);
    const float bzb  = 0.5f * (bi[i0+8+HID] + bh[i0+8+HID]);
    const float bnia = bi[i0+2*HID],          bnib = bi[i0+8+2*HID];
    const float bnha = bh[i0+2*HID],          bnhb = bh[i0+8+2*HID];

    float hprev[4];                      // (i0,n0),(i0,n1),(i1,n0),(i1,n1)
#pragma unroll
    for (int q = 0; q < 4; ++q) hprev[q] = 0.0f;

    const float* xs0 = (const float*)(smem + OFF_XS) + n0 * XS_STRIDE;
    const float* xs1 = xs0 + XS_STRIDE;

    // fragment-layout addressing
    // read: this thread's B pair (w=lane&3, w+4) is 8B-contiguous
    const char* pbrd = smem + (lane >> 2) * B_STRIDE + (lane & 3) * 8;
    // write: unit i0 -> byte fb, unit i0+8 -> fb+4 (within its n row)
    const int fb = wid * 32 + (((lane >> 2) >> 1) << 3) + ((lane >> 2) & 1) * 2;
    const char* wlo_base = smem + OFF_WLO + (wid * 3 * 8 * 32 + lane) * 16;

    __syncthreads();

#pragma unroll 1
    for (int t = 0; t < SEQ; ++t) {
        const int rsel = (t & 1) * 2176;
        const int wsel = ((t + 1) & 1) * 2176;

        float C[3][4];
#pragma unroll
        for (int j = 0; j < 3; ++j)
#pragma unroll
            for (int q = 0; q < 4; ++q) C[j][q] = 0.0f;

        const float xv0 = xs0[t];
        const float xv1 = xs1[t];

#pragma unroll
        for (int kt = 0; kt < 8; ++kt) {
            const uint2 hh = *(const uint2*)(pbrd + OFF_BH + rsel + kt * 32);
            const uint2 ll = *(const uint2*)(pbrd + OFF_BL + rsel + kt * 32);
#pragma unroll
            for (int j = 0; j < 3; ++j) {
                const uint4 wl = *(const uint4*)(wlo_base + (j * 8 + kt) * 512);
                mma16816(C[j], af[j][kt], hh.x, hh.y);        // W_hi * h_hi
                mma16816(C[j], af[j][kt], ll.x, ll.y);        // W_hi * h_lo
                const uint32_t wla[4] = {wl.x, wl.y, wl.z, wl.w};
                mma16816(C[j], wla, hh.x, hh.y);              // W_lo * h_hi
            }
        }

        // ---- gate math in registers (MUFU.TANH); store h hi/lo ----
        char* bhp = smem + OFF_BH + wsel;
        char* blp = smem + OFF_BL + wsel;
#pragma unroll
        for (int q = 0; q < 4; ++q) {
            const bool second = (q >= 2);
            const float xv  = (q & 1) ? xv1 : xv0;
            const int   n   = (q & 1) ? (n0 + 1) : n0;
            const float wiA = second ? wi0b : wi0a;
            const float wiB = second ? wi1b : wi1a;
            const float wiC = second ? wi2b : wi2a;
            const float bR  = second ? brb  : bra;
            const float bZ  = second ? bzb  : bza;
            const float bNi = second ? bnib : bnia;
            const float bNh = second ? bnhb : bnha;

            // r = sigmoid(C0 + xv*wi + b) = 0.5*tanh(0.5*(...)) + 0.5
            const float rr = fmaf(0.5f,
                mufu_tanh(fmaf(0.5f, C[0][q], fmaf(xv, wiA, bR))), 0.5f);
            const float zz = fmaf(0.5f,
                mufu_tanh(fmaf(0.5f, C[1][q], fmaf(xv, wiB, bZ))), 0.5f);
            const float nn =
                mufu_tanh(fmaf(xv, wiC, bNi) + rr * (C[2][q] + bNh));
            const float h = nn + zz * (hprev[q] - nn);
            hprev[q] = h;

            const uint16_t hb = f2bf(h);
            const uint16_t lb = f2bf(h - bf2f(hb));
            const int off = n * B_STRIDE + fb + (second ? 4 : 0);
            *(uint16_t*)(bhp + off) = hb;
            *(uint16_t*)(blp + off) = lb;
        }
        __syncthreads();
    }

    // ---- final FC: logits = h @ Wfc^T + bfc ----
    float* hf = (float*)(smem + OFF_XS);   // reuse: hf[i][n]
    {
        hf[i0 * ROWS + n0]           = hprev[0];
        hf[i0 * ROWS + n0 + 1]       = hprev[1];
        hf[(i0 + 8) * ROWS + n0]     = hprev[2];
        hf[(i0 + 8) * ROWS + n0 + 1] = hprev[3];
    }
    __syncthreads();

    if (tid < ROWS * 10) {
        const int r = tid / 10;
        const int o = tid - r * 10;
        float s = bfc[o];
        const float* wf = Wfc + o * HID;
#pragma unroll 8
        for (int k = 0; k < HID; ++k) s = fmaf(hf[k * ROWS + r], wf[k], s);
        out[(long)(row0 + r) * 10 + o] = s;
    }
}

extern "C" void kernel_launch(void* const* d_in, const int* in_sizes, int n_in,
                              void* d_out, int out_size) {
    const float* x   = (const float*)d_in[0];
    const float* Wi  = (const float*)d_in[1];
    const float* bi  = (const float*)d_in[2];
    const float* Wh  = (const float*)d_in[3];
    const float* bh  = (const float*)d_in[4];
    const float* Wfc = (const float*)d_in[5];
    const float* bfc = (const float*)d_in[6];
    float* out = (float*)d_out;

    cudaFuncSetAttribute(gru_hmma3_kernel,
                         cudaFuncAttributeMaxDynamicSharedMemorySize, SMEM_BYTES);
    gru_hmma3_kernel<<<NCTA, NT, SMEM_BYTES>>>(x, Wi, bi, Wh, bh, Wfc, bfc, out);
}